// round 2
// baseline (speedup 1.0000x reference)
#include <cuda_runtime.h>
#include <cstdint>
#include <cub/cub.cuh>

// Problem constants
#define C_DIM     4096
#define NUMEL_D   16777216.0
#define MAX_K     4500000          // >= S + R = 4,404,019
#define TEMP_BYTES (96u * 1024u * 1024u)

// Static device scratch (allocation-free per harness rules)
__device__ uint32_t g_ka[MAX_K];   // pass1 keys in  -> pass2 keys in (~ord)
__device__ uint32_t g_kb[MAX_K];   // pass1 keys out (sorted 24-bit keys)
__device__ uint32_t g_va[MAX_K];   // iota (values in for both passes)
__device__ uint32_t g_vb[MAX_K];   // pass1 values out (orig idx) -> pass2 values out (position)
__device__ uint32_t g_w [MAX_K];   // pass2 keys out (sorted ~ord)
__device__ unsigned char g_temp[TEMP_BYTES];

static __device__ __forceinline__ uint32_t f32_to_ord(uint32_t b) {
    // monotone increasing mapping of float bits
    return b ^ ((uint32_t)((int32_t)b >> 31) | 0x80000000u);
}

__global__ void pack_kernel(const int* __restrict__ samp,
                            const int* __restrict__ ridx,
                            int S, int K,
                            uint32_t* __restrict__ keys,
                            uint32_t* __restrict__ iota) {
    int i = blockIdx.x * blockDim.x + threadIdx.x;
    if (i >= K) return;
    uint32_t key;
    if (i < S) {
        key = (uint32_t)samp[i];
    } else {
        int r = i - S;
        key = (uint32_t)ridx[2 * r] * (uint32_t)C_DIM + (uint32_t)ridx[2 * r + 1];
    }
    keys[i] = key;
    iota[i] = (uint32_t)i;
}

// For each position j in key-sorted order: if j is the head of a key segment,
// sum that segment's values sequentially in ORIGINAL index order (stable sort
// guarantees ascending orig idx within a segment == scatter-add update order).
// Emit ~ord(sum) so that ascending stable sort == (value desc, key asc).
__global__ void headsum_kernel(const uint32_t* __restrict__ skeys,
                               const uint32_t* __restrict__ sidx,
                               const float* __restrict__ grad,
                               const float* __restrict__ rval,
                               int S, int K, float adj,
                               uint32_t* __restrict__ out_ord) {
    int j = blockIdx.x * blockDim.x + threadIdx.x;
    if (j >= K) return;
    uint32_t key = skeys[j];
    bool head = (j == 0) || (skeys[j - 1] != key);
    uint32_t sort_key;
    if (!head) {
        sort_key = 0xFFFFFFFFu;   // sorts after every head (all sums >= 0 -> ~ord <= 0x7FFFFFFF)
    } else {
        float sum = 0.0f;
        int t = j;
        while (t < K && skeys[t] == key) {
            uint32_t idx = sidx[t];
            float v = (idx < (uint32_t)S) ? fabsf(grad[idx])
                                          : adj * rval[idx - (uint32_t)S];
            sum += v;   // sequential, matches XLA scatter-add order
            ++t;
        }
        sort_key = ~f32_to_ord(__float_as_uint(sum));
    }
    out_ord[j] = sort_key;
}

__global__ void output_kernel(const uint32_t* __restrict__ sord,   // sorted ~ord
                              const uint32_t* __restrict__ spos,   // positions into key-sorted array
                              const uint32_t* __restrict__ skeys,  // key-sorted keys
                              int R, int write_idx, int write_val, int val_off,
                              float* __restrict__ out) {
    int r = blockIdx.x * blockDim.x + threadIdx.x;
    if (r >= R) return;
    uint32_t pos = spos[r];
    uint32_t key = skeys[pos];
    if (write_idx) {
        out[2 * r]     = (float)(key >> 12);
        out[2 * r + 1] = (float)(key & 4095u);
    }
    if (write_val) {
        uint32_t u = ~sord[r];     // recover ord bits
        uint32_t b = (u & 0x80000000u) ? (u ^ 0x80000000u) : ~u;
        out[val_off + r] = __uint_as_float(b);
    }
}

extern "C" void kernel_launch(void* const* d_in, const int* in_sizes, int n_in,
                              void* d_out, int out_size) {
    (void)n_in;
    const int*   samp = (const int*)d_in[0];     // sample_index [S] int32
    const int*   ridx = (const int*)d_in[1];     // result_index [R,2] int32
    const float* rval = (const float*)d_in[2];   // result_value [R] f32
    const float* grad = (const float*)d_in[3];   // gradient [S] f32

    int S = in_sizes[0];
    int R = in_sizes[2];
    int K = S + R;
    if (K > MAX_K) K = MAX_K;   // safety clamp (should never trigger)

    // adj_decay exactly as Python double math, rounded once to f32
    double frac = (double)S / NUMEL_D;
    float adj = (float)(1.0 - frac * (1.0 - 0.95));

    uint32_t *ka, *kb, *va, *vb, *w;
    void* tmp;
    cudaGetSymbolAddress((void**)&ka, g_ka);
    cudaGetSymbolAddress((void**)&kb, g_kb);
    cudaGetSymbolAddress((void**)&va, g_va);
    cudaGetSymbolAddress((void**)&vb, g_vb);
    cudaGetSymbolAddress((void**)&w,  g_w);
    cudaGetSymbolAddress(&tmp, g_temp);

    const int BLK = 256;

    // 1) Build (key, iota)
    pack_kernel<<<(K + BLK - 1) / BLK, BLK>>>(samp, ridx, S, K, ka, va);

    // 2) Stable sort by 24-bit key (values = original index)
    size_t need1 = 0;
    cub::DeviceRadixSort::SortPairs(nullptr, need1, ka, kb, va, vb,
                                    K, 0, 24);
    if (need1 <= (size_t)TEMP_BYTES)
        cub::DeviceRadixSort::SortPairs(tmp, need1, ka, kb, va, vb,
                                        K, 0, 24);

    // 3) Per-segment ordered sums -> descending-orderable keys (into ka)
    headsum_kernel<<<(K + BLK - 1) / BLK, BLK>>>(kb, vb, grad, rval, S, K, adj, ka);

    // 4) Stable sort by ~ord(sum): gives (value desc, key asc) exactly like lax.top_k
    size_t need2 = 0;
    cub::DeviceRadixSort::SortPairs(nullptr, need2, ka, w, va, vb,
                                    K, 0, 32);
    if (need2 <= (size_t)TEMP_BYTES)
        cub::DeviceRadixSort::SortPairs(tmp, need2, ka, w, va, vb,
                                        K, 0, 32);

    // 5) Emit top-R: layout = [new_index (R,2) as f32, top_vals (R) f32] when out_size==3R
    int write_idx = 1, write_val = 1, val_off = 2 * R;
    if (out_size == R)           { write_idx = 0; val_off = 0; }
    else if (out_size == 2 * R)  { write_val = 0; }
    output_kernel<<<(R + BLK - 1) / BLK, BLK>>>(w, vb, kb, R,
                                                write_idx, write_val, val_off,
                                                (float*)d_out);
}

// round 4
// speedup vs baseline: 1.1477x; 1.1477x over previous
#include <cuda_runtime.h>
#include <cstdint>
#include <cub/cub.cuh>

// Problem constants
#define C_DIM     4096
#define NUMEL_D   16777216.0
#define MAX_K     4500000               // >= S + R = 4,404,019
#define M_SORT    1310720               // R + 256K slack (candidate sort size, fixed for graph)
#define HIST_BINS (1u << 20)            // ordkey >> 11
#define TEMP_BYTES (96u * 1024u * 1024u)

// Static device scratch (allocation-free per harness rules)
__device__ uint32_t g_ka[MAX_K];   // pack keys -> scan out -> sort2 key out (sorted ordkeys)
__device__ uint32_t g_kb[MAX_K];   // sort1 key out (key-sorted keys) -> sort2 value out (sorted cand keys)
__device__ uint32_t g_va[MAX_K];   // pack value bits -> cand_ord
__device__ uint32_t g_vb[MAX_K];   // sort1 value out (value bits) -> flags -> cand_key
__device__ uint32_t g_w [MAX_K];   // per-position ordkey (heads real, non-heads 0xFFFFFFFF)
__device__ uint32_t g_hist[HIST_BINS];
__device__ uint32_t g_super[4096];
__device__ uint32_t g_B[1];
__device__ unsigned char g_temp[TEMP_BYTES];

static __device__ __forceinline__ uint32_t f32_to_ord(uint32_t b) {
    return b ^ ((uint32_t)((int32_t)b >> 31) | 0x80000000u);
}

__global__ void pack_kernel(const int* __restrict__ samp,
                            const int* __restrict__ ridx,
                            const float* __restrict__ grad,
                            const float* __restrict__ rval,
                            int S, int K, float adj,
                            uint32_t* __restrict__ keys,
                            uint32_t* __restrict__ vals) {
    int i = blockIdx.x * blockDim.x + threadIdx.x;
    if (i >= K) return;
    uint32_t key; float v;
    if (i < S) {
        key = (uint32_t)samp[i];
        v = fabsf(grad[i]);
    } else {
        int r = i - S;
        key = (uint32_t)ridx[2 * r] * (uint32_t)C_DIM + (uint32_t)ridx[2 * r + 1];
        v = adj * rval[r];
    }
    keys[i] = key;
    vals[i] = __float_as_uint(v);
}

// Per segment-head: sum values (already in original order thanks to stable
// sort) -> ~ord(sum); also histogram heads for threshold selection.
__global__ void headsum_kernel(const uint32_t* __restrict__ skeys,
                               const uint32_t* __restrict__ svals,
                               int K,
                               uint32_t* __restrict__ out_ord,
                               uint32_t* __restrict__ hist) {
    int j = blockIdx.x * blockDim.x + threadIdx.x;
    if (j >= K) return;
    uint32_t key = skeys[j];
    bool head = (j == 0) || (skeys[j - 1] != key);
    if (!head) {
        out_ord[j] = 0xFFFFFFFFu;
        return;
    }
    float sum = 0.0f;
    int t = j;
    while (t < K && skeys[t] == key) {
        sum += __uint_as_float(svals[t]);   // sequential, matches XLA scatter-add order
        ++t;
    }
    uint32_t ordk = ~f32_to_ord(__float_as_uint(sum));  // <= 0x7FFFFFFF (sum >= 0)
    out_ord[j] = ordk;
    atomicAdd(&hist[ordk >> 11], 1u);
}

__global__ void coarse_kernel(const uint32_t* __restrict__ hist,
                              uint32_t* __restrict__ super) {
    typedef cub::BlockReduce<uint32_t, 256> BR;
    __shared__ typename BR::TempStorage ts;
    uint32_t v = hist[blockIdx.x * 256 + threadIdx.x];
    uint32_t s = BR(ts).Sum(v);
    if (threadIdx.x == 0) super[blockIdx.x] = s;
}

// Single block: find smallest bin boundary B such that #heads with ordkey < B >= R.
__global__ void select_kernel(const uint32_t* __restrict__ super,
                              const uint32_t* __restrict__ hist,
                              uint32_t R, uint32_t* __restrict__ Bout) {
    typedef cub::BlockScan<uint32_t, 1024> BS;
    __shared__ typename BS::TempStorage ts;
    __shared__ uint32_t s_sb, s_base;
    if (threadIdx.x == 0) { s_sb = 0xFFFFFFFFu; s_base = 0; }
    __syncthreads();

    uint32_t items[4], incl[4];
    #pragma unroll
    for (int i = 0; i < 4; i++) items[i] = super[threadIdx.x * 4 + i];
    BS(ts).InclusiveSum(items, incl);
    #pragma unroll
    for (int i = 0; i < 4; i++) {
        uint32_t excl = incl[i] - items[i];
        if (incl[i] >= R && excl < R) {          // unique crossing superbin
            s_sb = threadIdx.x * 4 + i;
            s_base = excl;
        }
    }
    __syncthreads();
    if (s_sb == 0xFFFFFFFFu) {                   // pathological: fewer heads than R
        if (threadIdx.x == 0) Bout[0] = 0xFFFFFFFFu;
        return;
    }
    uint32_t sb = s_sb, base = s_base;
    __syncthreads();                              // before TempStorage reuse
    uint32_t h = (threadIdx.x < 256) ? hist[sb * 256 + threadIdx.x] : 0u;
    uint32_t inc1;
    BS(ts).InclusiveSum(h, inc1);
    if (threadIdx.x < 256) {
        uint32_t excl = inc1 - h;
        if (base + inc1 >= R && base + excl < R) {
            Bout[0] = ((sb * 256u + threadIdx.x) + 1u) << 11;
        }
    }
}

__global__ void flags_kernel(const uint32_t* __restrict__ ordk,
                             const uint32_t* __restrict__ Bp,
                             int K,
                             uint32_t* __restrict__ flags) {
    int j = blockIdx.x * blockDim.x + threadIdx.x;
    if (j >= K) return;
    flags[j] = (ordk[j] < *Bp) ? 1u : 0u;
}

__global__ void scatter_kernel(const uint32_t* __restrict__ ordk,
                               const uint32_t* __restrict__ scan,
                               const uint32_t* __restrict__ skeys,
                               const uint32_t* __restrict__ Bp,
                               int K,
                               uint32_t* __restrict__ cand_ord,
                               uint32_t* __restrict__ cand_key) {
    int j = blockIdx.x * blockDim.x + threadIdx.x;
    if (j >= K) return;
    uint32_t x = ordk[j];
    if (x < *Bp) {
        uint32_t p = scan[j];
        if (p < (uint32_t)M_SORT) {
            cand_ord[p] = x;
            cand_key[p] = skeys[j];
        }
    }
}

__global__ void output_kernel(const uint32_t* __restrict__ sord,   // sorted ordkeys
                              const uint32_t* __restrict__ skey,   // matching 24-bit keys
                              int R, int write_idx, int write_val, int val_off,
                              float* __restrict__ out) {
    int r = blockIdx.x * blockDim.x + threadIdx.x;
    if (r >= R) return;
    uint32_t key = skey[r];
    if (write_idx) {
        out[2 * r]     = (float)(key >> 12);
        out[2 * r + 1] = (float)(key & 4095u);
    }
    if (write_val) {
        uint32_t u = ~sord[r];
        uint32_t b = (u & 0x80000000u) ? (u ^ 0x80000000u) : ~u;
        out[val_off + r] = __uint_as_float(b);
    }
}

extern "C" void kernel_launch(void* const* d_in, const int* in_sizes, int n_in,
                              void* d_out, int out_size) {
    (void)n_in;
    const int*   samp = (const int*)d_in[0];
    const int*   ridx = (const int*)d_in[1];
    const float* rval = (const float*)d_in[2];
    const float* grad = (const float*)d_in[3];

    int S = in_sizes[0];
    int R = in_sizes[2];
    int K = S + R;
    if (K > MAX_K) K = MAX_K;

    double frac = (double)S / NUMEL_D;
    float adj = (float)(1.0 - frac * (1.0 - 0.95));

    uint32_t *ka, *kb, *va, *vb, *w, *hist, *super, *Bp;
    void* tmp;
    cudaGetSymbolAddress((void**)&ka, g_ka);
    cudaGetSymbolAddress((void**)&kb, g_kb);
    cudaGetSymbolAddress((void**)&va, g_va);
    cudaGetSymbolAddress((void**)&vb, g_vb);
    cudaGetSymbolAddress((void**)&w,  g_w);
    cudaGetSymbolAddress((void**)&hist, g_hist);
    cudaGetSymbolAddress((void**)&super, g_super);
    cudaGetSymbolAddress((void**)&Bp, g_B);
    cudaGetSymbolAddress(&tmp, g_temp);

    const int BLK = 256;
    const int GK = (K + BLK - 1) / BLK;

    // 0) zero histogram (graph replays need re-init each launch)
    cudaMemsetAsync(hist, 0, HIST_BINS * sizeof(uint32_t));

    // 1) Build (key, value-bits)
    pack_kernel<<<GK, BLK>>>(samp, ridx, grad, rval, S, K, adj, ka, va);

    // 2) Stable sort by 24-bit key, payload = value bits (preserves original order per key)
    {
        size_t need = 0;
        cub::DeviceRadixSort::SortPairs(nullptr, need, ka, kb, va, vb, K, 0, 24);
        if (need <= (size_t)TEMP_BYTES)
            cub::DeviceRadixSort::SortPairs(tmp, need, ka, kb, va, vb, K, 0, 24);
    }

    // 3) Ordered per-segment sums -> ordkey per position + histogram of heads
    headsum_kernel<<<GK, BLK>>>(kb, vb, K, w, hist);

    // 4) Threshold B (bin-granular, includes all ties of the R-th element)
    coarse_kernel<<<4096, 256>>>(hist, super);
    select_kernel<<<1, 1024>>>(super, hist, (uint32_t)R, Bp);

    // 5) Order-preserving compaction of candidates (keeps ascending-key order for ties)
    //    flags into vb (values are dead after headsum), scan into ka
    flags_kernel<<<GK, BLK>>>(w, Bp, K, vb);
    {
        size_t need = 0;
        cub::DeviceScan::ExclusiveSum(nullptr, need, vb, ka, K);
        if (need <= (size_t)TEMP_BYTES)
            cub::DeviceScan::ExclusiveSum(tmp, need, vb, ka, K);
    }

    // 6) Pad candidate buffers (entries past the real count sort to the end, never in top R)
    cudaMemsetAsync(va, 0xFF, (size_t)M_SORT * sizeof(uint32_t));
    cudaMemsetAsync(vb, 0xFF, (size_t)M_SORT * sizeof(uint32_t));

    scatter_kernel<<<GK, BLK>>>(w, ka, kb, Bp, K, va, vb);

    // 7) Stable sort candidates by ordkey (asc) == (value desc, key asc), payload = key
    {
        size_t need = 0;
        cub::DeviceRadixSort::SortPairs(nullptr, need, va, ka, vb, kb, M_SORT, 0, 32);
        if (need <= (size_t)TEMP_BYTES)
            cub::DeviceRadixSort::SortPairs(tmp, need, va, ka, vb, kb, M_SORT, 0, 32);
    }

    // 8) Emit [new_index (R,2), top_vals (R)] as f32
    int write_idx = 1, write_val = 1, val_off = 2 * R;
    if (out_size == R)          { write_idx = 0; val_off = 0; }
    else if (out_size == 2 * R) { write_val = 0; }
    output_kernel<<<(R + BLK - 1) / BLK, BLK>>>(ka, kb, R, write_idx, write_val, val_off,
                                                (float*)d_out);
}